// round 5
// baseline (speedup 1.0000x reference)
#include <cuda_runtime.h>
#include <cuda_bf16.h>
#include <math.h>
#include <cstdint>

#define NLAYER 6
#define DV     512      // d_model
#define NH     8
#define HD     64
#define DFF    2048
#define BB     8
#define LL     1024
#define MM     (BB*LL)  // 8192 rows
#define QKV_STRIDE (3*DV)

// ---------------- scratch (static device globals; no allocation) ----------------
__device__ float g_out [MM*DV];
__device__ float g_qkv [MM*3*DV];
__device__ float g_attn[MM*DV];
__device__ float g_tmp [MM*DV];
__device__ float g_h   [MM*DFF];
__device__ unsigned char g_kpm[MM];

// ---------------- packed f32x2 helpers (Blackwell baseline ISA) ----------------
typedef unsigned long long u64t;

__device__ __forceinline__ u64t fma2(u64t a, u64t b, u64t c) {
    u64t d;
    asm("fma.rn.f32x2 %0, %1, %2, %3;" : "=l"(d) : "l"(a), "l"(b), "l"(c));
    return d;
}
__device__ __forceinline__ u64t mul2(u64t a, u64t b) {
    u64t d;
    asm("mul.rn.f32x2 %0, %1, %2;" : "=l"(d) : "l"(a), "l"(b));
    return d;
}
__device__ __forceinline__ u64t pack2(float lo, float hi) {
    u64t r;
    unsigned l = __float_as_uint(lo), h = __float_as_uint(hi);
    asm("mov.b64 %0, {%1, %2};" : "=l"(r) : "r"(l), "r"(h));
    return r;
}
__device__ __forceinline__ u64t dup2(float x) { return pack2(x, x); }
__device__ __forceinline__ float2 unpk2(u64t v) {
    unsigned lo, hi;
    asm("mov.b64 {%0, %1}, %2;" : "=r"(lo), "=r"(hi) : "l"(v));
    return make_float2(__uint_as_float(lo), __uint_as_float(hi));
}

// ---------------- key padding mask ----------------
__global__ void kpm_kernel(const float* __restrict__ x, unsigned char* __restrict__ kpm)
{
    int row = blockIdx.x;
    int t = threadIdx.x;
    int nz = 0;
    for (int c = t; c < DV; c += 128)
        nz |= (x[(size_t)row * DV + c] != 0.0f) ? 1 : 0;
    nz = __syncthreads_or(nz);
    if (t == 0) kpm[row] = nz ? 0 : 1;
}

// ---------------- float4 copy ----------------
__global__ void copy_kernel(const float* __restrict__ src, float* __restrict__ dst, int n4)
{
    int i = blockIdx.x * blockDim.x + threadIdx.x;
    if (i < n4) ((float4*)dst)[i] = ((const float4*)src)[i];
}

// ---------------- SIMT fp32 GEMM with packed FFMA2 ----------------
// C[m,n] = sum_k A[m,k] * W[n,k] + bias[n]; A: M x K, W: N x K row-major.
// 128x128 tile, 256 threads, 8x8 per thread (rows paired into f32x2 lanes), K-tile 16.
template<bool GELU>
__global__ __launch_bounds__(256) void gemm_kernel(
    const float* __restrict__ A, const float* __restrict__ W,
    const float* __restrict__ bias, float* __restrict__ C,
    int M, int N, int K)
{
    __shared__ __align__(16) float As[16][128];
    __shared__ __align__(16) float Bs[16][128];
    const int bm = blockIdx.y * 128;
    const int bn = blockIdx.x * 128;
    const int t  = threadIdx.x;
    const int tm = (t >> 4) * 8;       // 0..120
    const int tn = (t & 15) * 8;       // 0..120

    // acc2[i2][j]: lane0 = row tm+2*i2, lane1 = row tm+2*i2+1, column tn+j
    u64t acc2[4][8];
#pragma unroll
    for (int i = 0; i < 4; i++)
#pragma unroll
        for (int j = 0; j < 8; j++) acc2[i][j] = 0ULL;

    for (int k0 = 0; k0 < K; k0 += 16) {
#pragma unroll
        for (int r = 0; r < 2; r++) {
            int idx = t + r * 256;            // 0..511 float4 slots
            int row = idx >> 2;               // 0..127
            int kv  = (idx & 3) << 2;         // 0,4,8,12
            float4 a4 = *(const float4*)(A + (size_t)(bm + row) * K + k0 + kv);
            As[kv+0][row] = a4.x; As[kv+1][row] = a4.y;
            As[kv+2][row] = a4.z; As[kv+3][row] = a4.w;
            float4 w4 = *(const float4*)(W + (size_t)(bn + row) * K + k0 + kv);
            Bs[kv+0][row] = w4.x; Bs[kv+1][row] = w4.y;
            Bs[kv+2][row] = w4.z; Bs[kv+3][row] = w4.w;
        }
        __syncthreads();
#pragma unroll
        for (int k = 0; k < 16; k++) {
            // a rows as natural f32x2 pairs
            ulonglong2 a01 = *(const ulonglong2*)&As[k][tm];      // rows tm..tm+3
            ulonglong2 a23 = *(const ulonglong2*)&As[k][tm + 4];  // rows tm+4..tm+7
            u64t ap[4] = { a01.x, a01.y, a23.x, a23.y };
            float4 b0 = *(const float4*)&Bs[k][tn];
            float4 b1 = *(const float4*)&Bs[k][tn + 4];
            u64t bd[8];
            bd[0] = dup2(b0.x); bd[1] = dup2(b0.y); bd[2] = dup2(b0.z); bd[3] = dup2(b0.w);
            bd[4] = dup2(b1.x); bd[5] = dup2(b1.y); bd[6] = dup2(b1.z); bd[7] = dup2(b1.w);
#pragma unroll
            for (int i = 0; i < 4; i++)
#pragma unroll
                for (int j = 0; j < 8; j++)
                    acc2[i][j] = fma2(ap[i], bd[j], acc2[i][j]);
        }
        __syncthreads();
    }

    float bb[8];
#pragma unroll
    for (int j = 0; j < 8; j++) bb[j] = bias[bn + tn + j];

#pragma unroll
    for (int i2 = 0; i2 < 4; i2++) {
        float r0[8], r1[8];
#pragma unroll
        for (int j = 0; j < 8; j++) {
            float2 v = unpk2(acc2[i2][j]);
            float v0 = v.x + bb[j];
            float v1 = v.y + bb[j];
            if (GELU) {
                v0 = 0.5f * v0 * (1.0f + erff(v0 * 0.70710678118654752f));
                v1 = 0.5f * v1 * (1.0f + erff(v1 * 0.70710678118654752f));
            }
            r0[j] = v0; r1[j] = v1;
        }
        size_t row0 = (size_t)(bm + tm + 2 * i2);
        *(float4*)(C + row0 * N + bn + tn)     = make_float4(r0[0], r0[1], r0[2], r0[3]);
        *(float4*)(C + row0 * N + bn + tn + 4) = make_float4(r0[4], r0[5], r0[6], r0[7]);
        *(float4*)(C + (row0 + 1) * N + bn + tn)     = make_float4(r1[0], r1[1], r1[2], r1[3]);
        *(float4*)(C + (row0 + 1) * N + bn + tn + 4) = make_float4(r1[4], r1[5], r1[6], r1[7]);
    }
}

// ---------------- flash-style causal attention with relative-position bias ----------------
// grid: (B*H, L/128); 128 threads; thread t owns query i = qbase + t. Packed f32x2 math.
#define KT 8
__global__ __launch_bounds__(128) void attn_kernel(
    const float* __restrict__ qkv, const float* __restrict__ dist_emb,
    const unsigned char* __restrict__ kpm, float* __restrict__ outp)
{
    __shared__ __align__(16) float sK[KT][HD];
    __shared__ __align__(16) float sV[KT][HD];
    __shared__ float sb[LL];
    __shared__ unsigned char skpm[LL];

    const int bh = blockIdx.x;
    const int b = bh / NH, h = bh % NH;
    const int qbase = blockIdx.y * 128;
    const int t = threadIdx.x;
    const int i = qbase + t;

    for (int d = t; d < LL; d += 128) {
        sb[d] = dist_emb[d * NH + h];
        skpm[d] = kpm[b * LL + d];
    }

    // q as 16 x ulonglong2 (32 f32x2 pairs over d)
    ulonglong2 qp[16];
    const ulonglong2* qg = (const ulonglong2*)(qkv + (size_t)(b * LL + i) * QKV_STRIDE + h * HD);
#pragma unroll
    for (int n = 0; n < 16; n++) qp[n] = qg[n];

    float m = -1e30f, lsum = 0.0f;
    u64t accp[32];
#pragma unroll
    for (int n = 0; n < 32; n++) accp[n] = 0ULL;

    __syncthreads();   // sb / skpm ready

    const float scale = 0.125f;   // 1/sqrt(64)
    const int jend = qbase + 128;

    for (int jt = 0; jt < jend; jt += KT) {
        {
            int krow = t >> 4;
            int kc   = (t & 15) * 4;
            const float* kp = qkv + (size_t)(b * LL + jt + krow) * QKV_STRIDE + DV   + h * HD + kc;
            const float* vp = qkv + (size_t)(b * LL + jt + krow) * QKV_STRIDE + 2*DV + h * HD + kc;
            *(float4*)&sK[krow][kc] = *(const float4*)kp;
            *(float4*)&sV[krow][kc] = *(const float4*)vp;
        }
        __syncthreads();

        float s[KT];
#pragma unroll
        for (int jj = 0; jj < KT; jj++) {
            int j = jt + jj;
            const ulonglong2* kr = (const ulonglong2*)&sK[jj][0];
            u64t d2a = 0ULL, d2b = 0ULL;
#pragma unroll
            for (int n = 0; n < 16; n++) {
                ulonglong2 kk = kr[n];
                d2a = fma2(qp[n].x, kk.x, d2a);
                d2b = fma2(qp[n].y, kk.y, d2b);
            }
            float2 fa = unpk2(d2a), fb = unpk2(d2b);
            float dotv = (fa.x + fa.y) + (fb.x + fb.y);
            float sc = -1e30f;
            if (j <= i && !skpm[j]) sc = dotv * scale + sb[i - j];
            s[jj] = sc;
        }
        float tmax = s[0];
#pragma unroll
        for (int jj = 1; jj < KT; jj++) tmax = fmaxf(tmax, s[jj]);
        float mnew = fmaxf(m, tmax);
        float alpha = (m > -1e29f) ? __expf(m - mnew) : 0.0f;
        lsum *= alpha;
        {
            u64t ad = dup2(alpha);
#pragma unroll
            for (int n = 0; n < 32; n++) accp[n] = mul2(accp[n], ad);
        }
#pragma unroll
        for (int jj = 0; jj < KT; jj++) {
            float p = (s[jj] > -1e29f) ? __expf(s[jj] - mnew) : 0.0f;
            lsum += p;
            u64t pd = dup2(p);
            const ulonglong2* vr = (const ulonglong2*)&sV[jj][0];
#pragma unroll
            for (int n = 0; n < 16; n++) {
                ulonglong2 vv = vr[n];
                accp[2*n]   = fma2(pd, vv.x, accp[2*n]);
                accp[2*n+1] = fma2(pd, vv.y, accp[2*n+1]);
            }
        }
        m = mnew;
        __syncthreads();
    }

    float inv = 1.0f / lsum;
    float* op = outp + (size_t)(b * LL + i) * DV + h * HD;
#pragma unroll
    for (int n = 0; n < 16; n++) {
        float2 e = unpk2(accp[2*n]);
        float2 o = unpk2(accp[2*n+1]);
        *(float4*)(op + 4*n) = make_float4(e.x * inv, e.y * inv, o.x * inv, o.y * inv);
    }
}

// ---------------- residual + LayerNorm ----------------
__global__ __launch_bounds__(128) void ln_kernel(
    const float* __restrict__ x, const float* __restrict__ res,
    const float* __restrict__ g, const float* __restrict__ beta,
    float* __restrict__ outp)
{
    const int row = blockIdx.x;
    const int t = threadIdx.x;
    const float* xr = x + (size_t)row * DV;

    float v[4];
#pragma unroll
    for (int k = 0; k < 4; k++) {
        int c = k * 128 + t;
        float val = xr[c];
        if (res) val += res[(size_t)row * DV + c];
        v[k] = val;
    }
    float s = 0.0f, ss = 0.0f;
#pragma unroll
    for (int k = 0; k < 4; k++) { s += v[k]; ss += v[k] * v[k]; }
#pragma unroll
    for (int o = 16; o > 0; o >>= 1) {
        s  += __shfl_xor_sync(0xFFFFFFFFu, s,  o);
        ss += __shfl_xor_sync(0xFFFFFFFFu, ss, o);
    }
    __shared__ float rs[4], rss[4];
    int w = t >> 5;
    if ((t & 31) == 0) { rs[w] = s; rss[w] = ss; }
    __syncthreads();
    s  = rs[0] + rs[1] + rs[2] + rs[3];
    ss = rss[0] + rss[1] + rss[2] + rss[3];
    float mean = s * (1.0f / DV);
    float var  = ss * (1.0f / DV) - mean * mean;
    float r = rsqrtf(var + 1e-5f);
#pragma unroll
    for (int k = 0; k < 4; k++) {
        int c = k * 128 + t;
        outp[(size_t)row * DV + c] = (v[k] - mean) * r * g[c] + beta[c];
    }
}

// ---------------- host launcher ----------------
extern "C" void kernel_launch(void* const* d_in, const int* in_sizes, int n_in,
                              void* d_out, int out_size)
{
    (void)in_sizes; (void)n_in; (void)out_size;
    const float* x         = (const float*)d_in[0];
    const float* dist_emb  = (const float*)d_in[1];
    const float* in_proj_w = (const float*)d_in[2];
    const float* in_proj_b = (const float*)d_in[3];
    const float* out_w     = (const float*)d_in[4];
    const float* out_b     = (const float*)d_in[5];
    const float* lin1_w    = (const float*)d_in[6];
    const float* lin1_b    = (const float*)d_in[7];
    const float* lin2_w    = (const float*)d_in[8];
    const float* lin2_b    = (const float*)d_in[9];
    const float* ln1_g     = (const float*)d_in[10];
    const float* ln1_bp    = (const float*)d_in[11];
    const float* ln2_g     = (const float*)d_in[12];
    const float* ln2_bp    = (const float*)d_in[13];
    const float* lnf_g     = (const float*)d_in[14];
    const float* lnf_bp    = (const float*)d_in[15];

    float *p_out, *p_qkv, *p_attn, *p_tmp, *p_h;
    unsigned char* p_kpm;
    cudaGetSymbolAddress((void**)&p_out,  g_out);
    cudaGetSymbolAddress((void**)&p_qkv,  g_qkv);
    cudaGetSymbolAddress((void**)&p_attn, g_attn);
    cudaGetSymbolAddress((void**)&p_tmp,  g_tmp);
    cudaGetSymbolAddress((void**)&p_h,    g_h);
    cudaGetSymbolAddress((void**)&p_kpm,  g_kpm);

    kpm_kernel<<<MM, 128>>>(x, p_kpm);
    {
        int n4 = MM * DV / 4;
        copy_kernel<<<(n4 + 255) / 256, 256>>>(x, p_out, n4);
    }

    for (int l = 0; l < NLAYER; l++) {
        const float* Wq  = in_proj_w + (size_t)l * 3 * DV * DV;
        const float* bq  = in_proj_b + (size_t)l * 3 * DV;
        const float* Wo  = out_w     + (size_t)l * DV * DV;
        const float* bo  = out_b     + (size_t)l * DV;
        const float* W1  = lin1_w    + (size_t)l * DFF * DV;
        const float* b1  = lin1_b    + (size_t)l * DFF;
        const float* W2  = lin2_w    + (size_t)l * DV * DFF;
        const float* b2  = lin2_b    + (size_t)l * DV;

        // QKV projection
        gemm_kernel<false><<<dim3(3 * DV / 128, MM / 128), 256>>>(p_out, Wq, bq, p_qkv, MM, 3 * DV, DV);
        // attention
        attn_kernel<<<dim3(BB * NH, LL / 128), 128>>>(p_qkv, dist_emb, p_kpm, p_attn);
        // output projection
        gemm_kernel<false><<<dim3(DV / 128, MM / 128), 256>>>(p_attn, Wo, bo, p_tmp, MM, DV, DV);
        // residual + LN1
        ln_kernel<<<MM, 128>>>(p_out, p_tmp, ln1_g + (size_t)l * DV, ln1_bp + (size_t)l * DV, p_out);
        // FFN
        gemm_kernel<true ><<<dim3(DFF / 128, MM / 128), 256>>>(p_out, W1, b1, p_h, MM, DFF, DV);
        gemm_kernel<false><<<dim3(DV / 128, MM / 128), 256>>>(p_h, W2, b2, p_tmp, MM, DV, DFF);
        // residual + LN2
        ln_kernel<<<MM, 128>>>(p_out, p_tmp, ln2_g + (size_t)l * DV, ln2_bp + (size_t)l * DV, p_out);
    }

    ln_kernel<<<MM, 128>>>(p_out, (const float*)nullptr, lnf_g, lnf_bp, (float*)d_out);
}

// round 6
// speedup vs baseline: 1.8009x; 1.8009x over previous
#include <cuda_runtime.h>
#include <cuda_bf16.h>
#include <math.h>
#include <cstdint>

#define NLAYER 6
#define DV     512
#define NH     8
#define HD     64
#define DFF    2048
#define BB     8
#define LL     1024
#define MM     (BB*LL)
#define QKV_STRIDE (3*DV)

// ---------------- scratch ----------------
__device__ float g_out [MM*DV];
__device__ float g_qkv [MM*3*DV];
__device__ float g_attn[MM*DV];
__device__ float g_tmp [MM*DV];
__device__ float g_h   [MM*DFF];
__device__ unsigned char g_kpm[MM];

#define W_IN_SZ   (NLAYER*3*DV*DV)
#define W_OUT_SZ  (NLAYER*DV*DV)
#define W_L1_SZ   (NLAYER*DFF*DV)
#define W_L2_SZ   (NLAYER*DV*DFF)
#define W_TOT     (W_IN_SZ+W_OUT_SZ+W_L1_SZ+W_L2_SZ)
#define OFF_IN    0
#define OFF_OUT   (W_IN_SZ)
#define OFF_L1    (W_IN_SZ+W_OUT_SZ)
#define OFF_L2    (W_IN_SZ+W_OUT_SZ+W_L1_SZ)
__device__ __nv_bfloat16 g_whib[W_TOT];
__device__ __nv_bfloat16 g_wlob[W_TOT];
__device__ __nv_bfloat16 g_ahib[MM*DFF];
__device__ __nv_bfloat16 g_alob[MM*DFF];

// ---------------- packed f32x2 helpers ----------------
typedef unsigned long long u64t;
__device__ __forceinline__ u64t fma2(u64t a, u64t b, u64t c) {
    u64t d; asm("fma.rn.f32x2 %0, %1, %2, %3;" : "=l"(d) : "l"(a), "l"(b), "l"(c)); return d;
}
__device__ __forceinline__ u64t mul2(u64t a, u64t b) {
    u64t d; asm("mul.rn.f32x2 %0, %1, %2;" : "=l"(d) : "l"(a), "l"(b)); return d;
}
__device__ __forceinline__ u64t pack2(float lo, float hi) {
    u64t r; unsigned l = __float_as_uint(lo), h = __float_as_uint(hi);
    asm("mov.b64 %0, {%1, %2};" : "=l"(r) : "r"(l), "r"(h)); return r;
}
__device__ __forceinline__ u64t dup2(float x) { return pack2(x, x); }
__device__ __forceinline__ float2 unpk2(u64t v) {
    unsigned lo, hi; asm("mov.b64 {%0, %1}, %2;" : "=r"(lo), "=r"(hi) : "l"(v));
    return make_float2(__uint_as_float(lo), __uint_as_float(hi));
}

// ---------------- smem / mma helpers ----------------
__device__ __forceinline__ uint32_t s2u(const void* p) {
    uint32_t a;
    asm("{ .reg .u64 t; cvta.to.shared.u64 t, %1; cvt.u32.u64 %0, t; }" : "=r"(a) : "l"(p));
    return a;
}
__device__ __forceinline__ void cpa16(uint32_t dst, const void* src) {
    asm volatile("cp.async.cg.shared.global [%0], [%1], 16;" :: "r"(dst), "l"(src) : "memory");
}
__device__ __forceinline__ void cpa_commit() { asm volatile("cp.async.commit_group;" ::: "memory"); }
__device__ __forceinline__ void cpa_wait0() { asm volatile("cp.async.wait_group 0;" ::: "memory"); }
__device__ __forceinline__ void cpa_wait1() { asm volatile("cp.async.wait_group 1;" ::: "memory"); }
__device__ __forceinline__ void ldmx4(uint32_t* r, uint32_t addr) {
    asm volatile("ldmatrix.sync.aligned.m8n8.x4.shared.b16 {%0,%1,%2,%3}, [%4];"
        : "=r"(r[0]), "=r"(r[1]), "=r"(r[2]), "=r"(r[3]) : "r"(addr));
}
__device__ __forceinline__ void mma_bf16(float* d, const uint32_t* a, const uint32_t* b) {
    asm volatile("mma.sync.aligned.m16n8k16.row.col.f32.bf16.bf16.f32 "
        "{%0,%1,%2,%3}, {%4,%5,%6,%7}, {%8,%9}, {%0,%1,%2,%3};"
        : "+f"(d[0]), "+f"(d[1]), "+f"(d[2]), "+f"(d[3])
        : "r"(a[0]), "r"(a[1]), "r"(a[2]), "r"(a[3]), "r"(b[0]), "r"(b[1]));
}

// ---------------- key padding mask ----------------
__global__ void kpm_kernel(const float* __restrict__ x, unsigned char* __restrict__ kpm)
{
    int row = blockIdx.x;
    int t = threadIdx.x;
    int nz = 0;
    for (int c = t; c < DV; c += 128)
        nz |= (x[(size_t)row * DV + c] != 0.0f) ? 1 : 0;
    nz = __syncthreads_or(nz);
    if (t == 0) kpm[row] = nz ? 0 : 1;
}

__global__ void copy_kernel(const float* __restrict__ src, float* __restrict__ dst, int n4)
{
    int i = blockIdx.x * blockDim.x + threadIdx.x;
    if (i < n4) ((float4*)dst)[i] = ((const float4*)src)[i];
}

// ---------------- bf16 hi/lo split ----------------
__global__ void splitb_kernel(const float* __restrict__ src,
                              __nv_bfloat16* __restrict__ hi,
                              __nv_bfloat16* __restrict__ lo, int n4)
{
    int i = blockIdx.x * blockDim.x + threadIdx.x;
    if (i >= n4) return;
    float4 v = ((const float4*)src)[i];
    __nv_bfloat16 h0 = __float2bfloat16_rn(v.x);
    __nv_bfloat16 h1 = __float2bfloat16_rn(v.y);
    __nv_bfloat16 h2 = __float2bfloat16_rn(v.z);
    __nv_bfloat16 h3 = __float2bfloat16_rn(v.w);
    __nv_bfloat16 l0 = __float2bfloat16_rn(v.x - __bfloat162float(h0));
    __nv_bfloat16 l1 = __float2bfloat16_rn(v.y - __bfloat162float(h1));
    __nv_bfloat16 l2 = __float2bfloat16_rn(v.z - __bfloat162float(h2));
    __nv_bfloat16 l3 = __float2bfloat16_rn(v.w - __bfloat162float(h3));
    __nv_bfloat162* hp = (__nv_bfloat162*)hi;
    __nv_bfloat162* lp = (__nv_bfloat162*)lo;
    hp[2*i]   = __nv_bfloat162(h0, h1);
    hp[2*i+1] = __nv_bfloat162(h2, h3);
    lp[2*i]   = __nv_bfloat162(l0, l1);
    lp[2*i+1] = __nv_bfloat162(l2, l3);
}

// ---------------- HMMA bf16 hi/lo GEMM ----------------
// C[m,n] = sum_k A[m,k]*W[n,k] + bias[n], fp32-accurate via 3-term bf16.
// 128x128 CTA tile, 256 thr (8 warps, 4x2), warp 32x64, BK=32, cp.async 2-stage.
// smem per stage 32KB: Ahi@0, Alo@8K, Bhi@16K, Blo@24K; row=64B, swizzled 16B chunks.
#define GSM_STAGE 32768
#define GSM_TOTAL (2*GSM_STAGE)

__device__ __forceinline__ uint32_t swz(int row, int kch) {
    return (uint32_t)(row * 64 + (((kch + ((row >> 1) & 3)) & 3) << 4));
}

template<bool GELU>
__global__ __launch_bounds__(256) void hmma_gemm(
    const __nv_bfloat16* __restrict__ Ahi, const __nv_bfloat16* __restrict__ Alo,
    const __nv_bfloat16* __restrict__ Whi, const __nv_bfloat16* __restrict__ Wlo,
    const float* __restrict__ bias, float* __restrict__ C, int N, int K)
{
    extern __shared__ __align__(16) char sm[];
    const uint32_t sb = s2u(sm);
    const int t = threadIdx.x;
    const int bm = blockIdx.y * 128, bn = blockIdx.x * 128;
    const int w = t >> 5, l = t & 31;
    const int wm = w & 3, wn = w >> 2;

    float acc[2][8][4];
#pragma unroll
    for (int mt = 0; mt < 2; mt++)
#pragma unroll
        for (int nt = 0; nt < 8; nt++)
#pragma unroll
            for (int e = 0; e < 4; e++) acc[mt][nt][e] = 0.0f;

    const int nch = K >> 5;

    // stage loader: thread t loads 16B chunks ch = t, t+256 for each component
    auto load_stage = [&](int stage, int kt) {
        const uint32_t base = sb + stage * GSM_STAGE;
        const int k0 = kt << 5;
#pragma unroll
        for (int q = 0; q < 2; q++) {
            int ch = t + (q << 8);
            int row = ch >> 2, c = ch & 3;
            uint32_t so = swz(row, c);
            size_t ga = (size_t)(bm + row) * K + k0 + c * 8;
            size_t gb = (size_t)(bn + row) * K + k0 + c * 8;
            cpa16(base + so,          Ahi + ga);
            cpa16(base + 8192 + so,   Alo + ga);
            cpa16(base + 16384 + so,  Whi + gb);
            cpa16(base + 24576 + so,  Wlo + gb);
        }
        cpa_commit();
    };

    load_stage(0, 0);

    for (int c = 0; c < nch; ++c) {
        if (c + 1 < nch) { load_stage((c + 1) & 1, c + 1); cpa_wait1(); }
        else             { cpa_wait0(); }
        __syncthreads();

        const uint32_t base = sb + (c & 1) * GSM_STAGE;
#pragma unroll
        for (int kk = 0; kk < 2; kk++) {
            uint32_t ah[2][4], al[2][4];
#pragma unroll
            for (int mt = 0; mt < 2; mt++) {
                int row = wm * 32 + mt * 16 + (l & 15);
                int kch = kk * 2 + (l >> 4);
                uint32_t off = swz(row, kch);
                ldmx4(ah[mt], base + off);
                ldmx4(al[mt], base + 8192 + off);
            }
            uint32_t bh[8][2], bl[8][2];
#pragma unroll
            for (int nt2 = 0; nt2 < 4; nt2++) {
                int row = wn * 64 + nt2 * 16 + (l & 7) + ((l >> 4) << 3);
                int kch = kk * 2 + ((l >> 3) & 1);
                uint32_t off = swz(row, kch);
                uint32_t r[4];
                ldmx4(r, base + 16384 + off);
                bh[nt2*2][0] = r[0]; bh[nt2*2][1] = r[1];
                bh[nt2*2+1][0] = r[2]; bh[nt2*2+1][1] = r[3];
                ldmx4(r, base + 24576 + off);
                bl[nt2*2][0] = r[0]; bl[nt2*2][1] = r[1];
                bl[nt2*2+1][0] = r[2]; bl[nt2*2+1][1] = r[3];
            }
#pragma unroll
            for (int mt = 0; mt < 2; mt++)
#pragma unroll
                for (int nt = 0; nt < 8; nt++) {
                    mma_bf16(acc[mt][nt], ah[mt], bh[nt]);
                    mma_bf16(acc[mt][nt], ah[mt], bl[nt]);
                    mma_bf16(acc[mt][nt], al[mt], bh[nt]);
                }
        }
        __syncthreads();
    }

    // epilogue
#pragma unroll
    for (int mt = 0; mt < 2; mt++) {
        int row = bm + wm * 32 + mt * 16 + (l >> 2);
#pragma unroll
        for (int nt = 0; nt < 8; nt++) {
            int col = bn + wn * 64 + nt * 8 + 2 * (l & 3);
            float b0 = bias[col], b1 = bias[col + 1];
            float v0 = acc[mt][nt][0] + b0;
            float v1 = acc[mt][nt][1] + b1;
            float v2 = acc[mt][nt][2] + b0;
            float v3 = acc[mt][nt][3] + b1;
            if (GELU) {
                v0 = 0.5f * v0 * (1.0f + erff(v0 * 0.70710678118654752f));
                v1 = 0.5f * v1 * (1.0f + erff(v1 * 0.70710678118654752f));
                v2 = 0.5f * v2 * (1.0f + erff(v2 * 0.70710678118654752f));
                v3 = 0.5f * v3 * (1.0f + erff(v3 * 0.70710678118654752f));
            }
            *(float2*)(C + (size_t)row * N + col)       = make_float2(v0, v1);
            *(float2*)(C + (size_t)(row + 8) * N + col) = make_float2(v2, v3);
        }
    }
}

// ---------------- flash-style causal attention (f32x2) ----------------
#define KT 8
__global__ __launch_bounds__(128) void attn_kernel(
    const float* __restrict__ qkv, const float* __restrict__ dist_emb,
    const unsigned char* __restrict__ kpm, float* __restrict__ outp)
{
    __shared__ __align__(16) float sK[KT][HD];
    __shared__ __align__(16) float sV[KT][HD];
    __shared__ float sb[LL];
    __shared__ unsigned char skpm[LL];

    const int bh = blockIdx.x;
    const int b = bh / NH, h = bh % NH;
    const int qbase = blockIdx.y * 128;
    const int t = threadIdx.x;
    const int i = qbase + t;

    for (int d = t; d < LL; d += 128) {
        sb[d] = dist_emb[d * NH + h];
        skpm[d] = kpm[b * LL + d];
    }

    ulonglong2 qp[16];
    const ulonglong2* qg = (const ulonglong2*)(qkv + (size_t)(b * LL + i) * QKV_STRIDE + h * HD);
#pragma unroll
    for (int n = 0; n < 16; n++) qp[n] = qg[n];

    float m = -1e30f, lsum = 0.0f;
    u64t accp[32];
#pragma unroll
    for (int n = 0; n < 32; n++) accp[n] = 0ULL;

    __syncthreads();

    const float scale = 0.125f;
    const int jend = qbase + 128;

    for (int jt = 0; jt < jend; jt += KT) {
        {
            int krow = t >> 4;
            int kc   = (t & 15) * 4;
            const float* kp = qkv + (size_t)(b * LL + jt + krow) * QKV_STRIDE + DV   + h * HD + kc;
            const float* vp = qkv + (size_t)(b * LL + jt + krow) * QKV_STRIDE + 2*DV + h * HD + kc;
            *(float4*)&sK[krow][kc] = *(const float4*)kp;
            *(float4*)&sV[krow][kc] = *(const float4*)vp;
        }
        __syncthreads();

        float s[KT];
#pragma unroll
        for (int jj = 0; jj < KT; jj++) {
            int j = jt + jj;
            const ulonglong2* kr = (const ulonglong2*)&sK[jj][0];
            u64t d2a = 0ULL, d2b = 0ULL;
#pragma unroll
            for (int n = 0; n < 16; n++) {
                ulonglong2 kk = kr[n];
                d2a = fma2(qp[n].x, kk.x, d2a);
                d2b = fma2(qp[n].y, kk.y, d2b);
            }
            float2 fa = unpk2(d2a), fb = unpk2(d2b);
            float dotv = (fa.x + fa.y) + (fb.x + fb.y);
            float sc = -1e30f;
            if (j <= i && !skpm[j]) sc = dotv * scale + sb[i - j];
            s[jj] = sc;
        }
        float tmax = s[0];
#pragma unroll
        for (int jj = 1; jj < KT; jj++) tmax = fmaxf(tmax, s[jj]);
        float mnew = fmaxf(m, tmax);
        float alpha = (m > -1e29f) ? __expf(m - mnew) : 0.0f;
        lsum *= alpha;
        {
            u64t ad = dup2(alpha);
#pragma unroll
            for (int n = 0; n < 32; n++) accp[n] = mul2(accp[n], ad);
        }
#pragma unroll
        for (int jj = 0; jj < KT; jj++) {
            float p = (s[jj] > -1e29f) ? __expf(s[jj] - mnew) : 0.0f;
            lsum += p;
            u64t pd = dup2(p);
            const ulonglong2* vr = (const ulonglong2*)&sV[jj][0];
#pragma unroll
            for (int n = 0; n < 16; n++) {
                ulonglong2 vv = vr[n];
                accp[2*n]   = fma2(pd, vv.x, accp[2*n]);
                accp[2*n+1] = fma2(pd, vv.y, accp[2*n+1]);
            }
        }
        m = mnew;
        __syncthreads();
    }

    float inv = 1.0f / lsum;
    float* op = outp + (size_t)(b * LL + i) * DV + h * HD;
#pragma unroll
    for (int n = 0; n < 16; n++) {
        float2 e = unpk2(accp[2*n]);
        float2 o = unpk2(accp[2*n+1]);
        *(float4*)(op + 4*n) = make_float4(e.x * inv, e.y * inv, o.x * inv, o.y * inv);
    }
}

// ---------------- residual + LayerNorm ----------------
__global__ __launch_bounds__(128) void ln_kernel(
    const float* __restrict__ x, const float* __restrict__ res,
    const float* __restrict__ g, const float* __restrict__ beta,
    float* __restrict__ outp)
{
    const int row = blockIdx.x;
    const int t = threadIdx.x;
    const float* xr = x + (size_t)row * DV;

    float v[4];
#pragma unroll
    for (int k = 0; k < 4; k++) {
        int c = k * 128 + t;
        float val = xr[c];
        if (res) val += res[(size_t)row * DV + c];
        v[k] = val;
    }
    float s = 0.0f, ss = 0.0f;
#pragma unroll
    for (int k = 0; k < 4; k++) { s += v[k]; ss += v[k] * v[k]; }
#pragma unroll
    for (int o = 16; o > 0; o >>= 1) {
        s  += __shfl_xor_sync(0xFFFFFFFFu, s,  o);
        ss += __shfl_xor_sync(0xFFFFFFFFu, ss, o);
    }
    __shared__ float rs[4], rss[4];
    int w = t >> 5;
    if ((t & 31) == 0) { rs[w] = s; rss[w] = ss; }
    __syncthreads();
    s  = rs[0] + rs[1] + rs[2] + rs[3];
    ss = rss[0] + rss[1] + rss[2] + rss[3];
    float mean = s * (1.0f / DV);
    float var  = ss * (1.0f / DV) - mean * mean;
    float r = rsqrtf(var + 1e-5f);
#pragma unroll
    for (int k = 0; k < 4; k++) {
        int c = k * 128 + t;
        outp[(size_t)row * DV + c] = (v[k] - mean) * r * g[c] + beta[c];
    }
}

// ---------------- host launcher ----------------
extern "C" void kernel_launch(void* const* d_in, const int* in_sizes, int n_in,
                              void* d_out, int out_size)
{
    (void)in_sizes; (void)n_in; (void)out_size;
    const float* x         = (const float*)d_in[0];
    const float* dist_emb  = (const float*)d_in[1];
    const float* in_proj_w = (const float*)d_in[2];
    const float* in_proj_b = (const float*)d_in[3];
    const float* out_w     = (const float*)d_in[4];
    const float* out_b     = (const float*)d_in[5];
    const float* lin1_w    = (const float*)d_in[6];
    const float* lin1_b    = (const float*)d_in[7];
    const float* lin2_w    = (const float*)d_in[8];
    const float* lin2_b    = (const float*)d_in[9];
    const float* ln1_g     = (const float*)d_in[10];
    const float* ln1_bp    = (const float*)d_in[11];
    const float* ln2_g     = (const float*)d_in[12];
    const float* ln2_bp    = (const float*)d_in[13];
    const float* lnf_g     = (const float*)d_in[14];
    const float* lnf_bp    = (const float*)d_in[15];

    float *p_out, *p_qkv, *p_attn, *p_tmp, *p_h;
    __nv_bfloat16 *p_whi, *p_wlo, *p_ahi, *p_alo;
    unsigned char* p_kpm;
    cudaGetSymbolAddress((void**)&p_out,  g_out);
    cudaGetSymbolAddress((void**)&p_qkv,  g_qkv);
    cudaGetSymbolAddress((void**)&p_attn, g_attn);
    cudaGetSymbolAddress((void**)&p_tmp,  g_tmp);
    cudaGetSymbolAddress((void**)&p_h,    g_h);
    cudaGetSymbolAddress((void**)&p_whi,  g_whib);
    cudaGetSymbolAddress((void**)&p_wlo,  g_wlob);
    cudaGetSymbolAddress((void**)&p_ahi,  g_ahib);
    cudaGetSymbolAddress((void**)&p_alo,  g_alob);
    cudaGetSymbolAddress((void**)&p_kpm,  g_kpm);

    cudaFuncSetAttribute(hmma_gemm<false>, cudaFuncAttributeMaxDynamicSharedMemorySize, GSM_TOTAL);
    cudaFuncSetAttribute(hmma_gemm<true>,  cudaFuncAttributeMaxDynamicSharedMemorySize, GSM_TOTAL);

    kpm_kernel<<<MM, 128>>>(x, p_kpm);
    {
        int n4 = MM * DV / 4;
        copy_kernel<<<(n4 + 255) / 256, 256>>>(x, p_out, n4);
    }

    // split weights once
    {
        int n4;
        n4 = W_IN_SZ  / 4; splitb_kernel<<<(n4 + 255) / 256, 256>>>(in_proj_w, p_whi + OFF_IN,  p_wlo + OFF_IN,  n4);
        n4 = W_OUT_SZ / 4; splitb_kernel<<<(n4 + 255) / 256, 256>>>(out_w,     p_whi + OFF_OUT, p_wlo + OFF_OUT, n4);
        n4 = W_L1_SZ  / 4; splitb_kernel<<<(n4 + 255) / 256, 256>>>(lin1_w,    p_whi + OFF_L1,  p_wlo + OFF_L1,  n4);
        n4 = W_L2_SZ  / 4; splitb_kernel<<<(n4 + 255) / 256, 256>>>(lin2_w,    p_whi + OFF_L2,  p_wlo + OFF_L2,  n4);
    }

    const int nA  = MM * DV / 4;
    const int nH4 = MM * DFF / 4;

    for (int l = 0; l < NLAYER; l++) {
        const __nv_bfloat16* whi_in = p_whi + OFF_IN  + (size_t)l * 3 * DV * DV;
        const __nv_bfloat16* wlo_in = p_wlo + OFF_IN  + (size_t)l * 3 * DV * DV;
        const __nv_bfloat16* whi_o  = p_whi + OFF_OUT + (size_t)l * DV * DV;
        const __nv_bfloat16* wlo_o  = p_wlo + OFF_OUT + (size_t)l * DV * DV;
        const __nv_bfloat16* whi_1  = p_whi + OFF_L1  + (size_t)l * DFF * DV;
        const __nv_bfloat16* wlo_1  = p_wlo + OFF_L1  + (size_t)l * DFF * DV;
        const __nv_bfloat16* whi_2  = p_whi + OFF_L2  + (size_t)l * DV * DFF;
        const __nv_bfloat16* wlo_2  = p_wlo + OFF_L2  + (size_t)l * DV * DFF;
        const float* bq  = in_proj_b + (size_t)l * 3 * DV;
        const float* bo  = out_b     + (size_t)l * DV;
        const float* b1  = lin1_b    + (size_t)l * DFF;
        const float* b2  = lin2_b    + (size_t)l * DV;

        // QKV projection
        splitb_kernel<<<(nA + 255) / 256, 256>>>(p_out, p_ahi, p_alo, nA);
        hmma_gemm<false><<<dim3(3 * DV / 128, MM / 128), 256, GSM_TOTAL>>>(
            p_ahi, p_alo, whi_in, wlo_in, bq, p_qkv, 3 * DV, DV);
        // attention
        attn_kernel<<<dim3(BB * NH, LL / 128), 128>>>(p_qkv, dist_emb, p_kpm, p_attn);
        // output projection
        splitb_kernel<<<(nA + 255) / 256, 256>>>(p_attn, p_ahi, p_alo, nA);
        hmma_gemm<false><<<dim3(DV / 128, MM / 128), 256, GSM_TOTAL>>>(
            p_ahi, p_alo, whi_o, wlo_o, bo, p_tmp, DV, DV);
        // residual + LN1
        ln_kernel<<<MM, 128>>>(p_out, p_tmp, ln1_g + (size_t)l * DV, ln1_bp + (size_t)l * DV, p_out);
        // FFN up (gelu)
        splitb_kernel<<<(nA + 255) / 256, 256>>>(p_out, p_ahi, p_alo, nA);
        hmma_gemm<true><<<dim3(DFF / 128, MM / 128), 256, GSM_TOTAL>>>(
            p_ahi, p_alo, whi_1, wlo_1, b1, p_h, DFF, DV);
        // FFN down
        splitb_kernel<<<(nH4 + 255) / 256, 256>>>(p_h, p_ahi, p_alo, nH4);
        hmma_gemm<false><<<dim3(DV / 128, MM / 128), 256, GSM_TOTAL>>>(
            p_ahi, p_alo, whi_2, wlo_2, b2, p_tmp, DV, DFF);
        // residual + LN2
        ln_kernel<<<MM, 128>>>(p_out, p_tmp, ln2_g + (size_t)l * DV, ln2_bp + (size_t)l * DV, p_out);
    }

    ln_kernel<<<MM, 128>>>(p_out, (const float*)nullptr, lnf_g, lnf_bp, (float*)d_out);
}